// round 5
// baseline (speedup 1.0000x reference)
#include <cuda_runtime.h>
#include <cuda_fp16.h>
#include <math_constants.h>

#define BB 2
#define SS 2048
#define DD 1024
#define HH 16
#define DK 64

// Scratch (allocation-free: __device__ globals)
__device__ float g_q[(size_t)BB * SS * DD];
__device__ float g_k[(size_t)BB * SS * DD];
__device__ float g_v[(size_t)BB * SS * DD];
__device__ float g_ctx[(size_t)BB * SS * DD];
__device__ float g_po[(size_t)BB * SS * DD];
__device__ float g_attn[(size_t)BB * HH * SS * SS];

__device__ __forceinline__ float ex2f(float x) {
    float y;
    asm("ex2.approx.ftz.f32 %0, %1;" : "=f"(y) : "f"(x));
    return y;
}

__device__ __forceinline__ void mma_fp16(float* c, const unsigned* a, unsigned b0, unsigned b1) {
    asm volatile(
        "mma.sync.aligned.m16n8k16.row.col.f32.f16.f16.f32 "
        "{%0,%1,%2,%3}, {%4,%5,%6,%7}, {%8,%9}, {%0,%1,%2,%3};\n"
        : "+f"(c[0]), "+f"(c[1]), "+f"(c[2]), "+f"(c[3])
        : "r"(a[0]), "r"(a[1]), "r"(a[2]), "r"(a[3]), "r"(b0), "r"(b1));
}

__device__ __forceinline__ void ldsm4(unsigned* r, unsigned addr) {
    asm volatile("ldmatrix.sync.aligned.m8n8.x4.shared.b16 {%0,%1,%2,%3}, [%4];"
                 : "=r"(r[0]), "=r"(r[1]), "=r"(r[2]), "=r"(r[3]) : "r"(addr));
}

__device__ __forceinline__ void ldsm4t(unsigned* r, unsigned addr) {
    asm volatile("ldmatrix.sync.aligned.m8n8.x4.trans.shared.b16 {%0,%1,%2,%3}, [%4];"
                 : "=r"(r[0]), "=r"(r[1]), "=r"(r[2]), "=r"(r[3]) : "r"(addr));
}

__device__ __forceinline__ void st_h4(__half* dst, float4 v) {
    __half2 h0 = __floats2half2_rn(v.x, v.y);
    __half2 h1 = __floats2half2_rn(v.z, v.w);
    *(uint2*)dst = make_uint2(*(unsigned*)&h0, *(unsigned*)&h1);
}

#define EXS 0.18033688f  /* 0.125 * log2(e) */

// smem strides in halves: stride*2 mod 128 == 16 -> conflict-free ldmatrix rows
#define QSP 72
#define KSP 72
#define VSP 72
#define PSP 136

#define SM_QS 0
#define SM_KS 4608          /* 64*72  */
#define SM_VS 13824         /* +128*72 */
#define SM_PS 23040         /* +128*72 */
#define SM_ENDH 31744       /* +64*136 */
#define SM_BYTES (SM_ENDH * 2 + 64 * 4)   /* + rs[64] floats = 63744 B */

// ---------------------------------------------------------------------------
// Fused attention, fp16 MMA path. 64 q rows per CTA, 256 threads (8 warps 2x4),
// 2 CTAs/SM. pass1 = row sums; pass2 = recompute, normalize, write attn, PV.
// ---------------------------------------------------------------------------
template <bool WRITE_ATTN>
__global__ __launch_bounds__(256, 2) void attn_kernel(
    const float* __restrict__ q, const float* __restrict__ k,
    const float* __restrict__ v, float* __restrict__ attn,
    float* __restrict__ ctx)
{
    extern __shared__ __half smh[];
    __half* Qs = smh + SM_QS;   // [64][QSP]   q rows x dk
    __half* Ks = smh + SM_KS;   // [128][KSP]  k rows x dk
    __half* Vs = smh + SM_VS;   // [128][VSP]  kseq rows x d (native)
    __half* Ps = smh + SM_PS;   // [64][PSP]   q rows x kseq
    float* rs  = (float*)(smh + SM_ENDH);  // [64]

    const unsigned smu = (unsigned)__cvta_generic_to_shared(smh);
    const unsigned QsU = smu + SM_QS * 2;
    const unsigned KsU = smu + SM_KS * 2;
    const unsigned VsU = smu + SM_VS * 2;
    const unsigned PsU = smu + SM_PS * 2;

    const int z = blockIdx.y;
    const int b = z >> 4, h = z & 15;
    const size_t base = (size_t)b * SS * DD + (size_t)h * DK;
    const int q0 = blockIdx.x * 64;

    const float* qp = q + base + (size_t)q0 * DD;
    const float* kp = k + base;
    const float* vp = v + base;
    float* attp = attn + (size_t)z * SS * SS + (size_t)q0 * SS;

    const int tid = threadIdx.x;
    const int warp = tid >> 5, l = tid & 31;
    const int gid = l >> 2, tig = l & 3;
    const int wm = warp >> 2, wn = warp & 3;   // 2 x 4

    // shared ldmatrix lane pattern (A, B-nontrans, B-trans all use it)
    const int arow  = (l & 7) + ((l >> 3) & 1) * 8;
    const int acolh = (l >> 4) * 8;

    // loaders
    const int lr = tid >> 1;          // 0..127
    const int lc = (tid & 1) * 32;    // 0 / 32
    const int qr = tid >> 2;          // 0..63
    const int qc = (tid & 3) * 16;

    // ---- Q tile 64x64 -> fp16 ----
    #pragma unroll
    for (int i = 0; i < 4; i++) {
        const float4 a = *(const float4*)(qp + (size_t)qr * DD + qc + i * 4);
        st_h4(&Qs[qr * QSP + qc + i * 4], a);
    }
    if (tid < 64) rs[tid] = 0.f;

    float rsum[2][2] = {};

    // =================== PASS 1: row sums ===================
    for (int kt = 0; kt < SS / 128; kt++) {
        __syncthreads();
        #pragma unroll
        for (int i = 0; i < 8; i++) {
            const float4 t = *(const float4*)(kp + (size_t)(kt * 128 + lr) * DD + lc + i * 4);
            st_h4(&Ks[lr * KSP + lc + i * 4], t);
        }
        __syncthreads();

        float c[2][4][4] = {};
        #pragma unroll
        for (int kk = 0; kk < DK; kk += 16) {
            unsigned af[2][4], bf[2][4];
            ldsm4(af[0], QsU + ((wm * 32 + arow) * QSP + kk + acolh) * 2);
            ldsm4(af[1], QsU + ((wm * 32 + 16 + arow) * QSP + kk + acolh) * 2);
            ldsm4(bf[0], KsU + ((wn * 32 + arow) * KSP + kk + acolh) * 2);
            ldsm4(bf[1], KsU + ((wn * 32 + 16 + arow) * KSP + kk + acolh) * 2);
            #pragma unroll
            for (int mt = 0; mt < 2; mt++) {
                mma_fp16(c[mt][0], af[mt], bf[0][0], bf[0][2]);
                mma_fp16(c[mt][1], af[mt], bf[0][1], bf[0][3]);
                mma_fp16(c[mt][2], af[mt], bf[1][0], bf[1][2]);
                mma_fp16(c[mt][3], af[mt], bf[1][1], bf[1][3]);
            }
        }
        #pragma unroll
        for (int mt = 0; mt < 2; mt++)
            #pragma unroll
            for (int nt = 0; nt < 4; nt++) {
                rsum[mt][0] += ex2f(c[mt][nt][0] * EXS) + ex2f(c[mt][nt][1] * EXS);
                rsum[mt][1] += ex2f(c[mt][nt][2] * EXS) + ex2f(c[mt][nt][3] * EXS);
            }
    }

    #pragma unroll
    for (int mt = 0; mt < 2; mt++)
        #pragma unroll
        for (int hf = 0; hf < 2; hf++) {
            float v0 = rsum[mt][hf];
            v0 += __shfl_xor_sync(0xffffffffu, v0, 1);
            v0 += __shfl_xor_sync(0xffffffffu, v0, 2);
            if (tig == 0) atomicAdd(&rs[wm * 32 + mt * 16 + hf * 8 + gid], v0);
        }
    __syncthreads();

    float inv[2][2];
    #pragma unroll
    for (int mt = 0; mt < 2; mt++)
        #pragma unroll
        for (int hf = 0; hf < 2; hf++)
            inv[mt][hf] = 1.0f / rs[wm * 32 + mt * 16 + hf * 8 + gid];

    float cacc[2][2][4] = {};

    // =================== PASS 2 ===================
    for (int kt = 0; kt < SS / 128; kt++) {
        __syncthreads();
        #pragma unroll
        for (int i = 0; i < 8; i++) {
            const float4 t = *(const float4*)(kp + (size_t)(kt * 128 + lr) * DD + lc + i * 4);
            st_h4(&Ks[lr * KSP + lc + i * 4], t);
            const float4 u = *(const float4*)(vp + (size_t)(kt * 128 + lr) * DD + lc + i * 4);
            st_h4(&Vs[lr * VSP + lc + i * 4], u);
        }
        __syncthreads();

        float c[2][4][4] = {};
        #pragma unroll
        for (int kk = 0; kk < DK; kk += 16) {
            unsigned af[2][4], bf[2][4];
            ldsm4(af[0], QsU + ((wm * 32 + arow) * QSP + kk + acolh) * 2);
            ldsm4(af[1], QsU + ((wm * 32 + 16 + arow) * QSP + kk + acolh) * 2);
            ldsm4(bf[0], KsU + ((wn * 32 + arow) * KSP + kk + acolh) * 2);
            ldsm4(bf[1], KsU + ((wn * 32 + 16 + arow) * KSP + kk + acolh) * 2);
            #pragma unroll
            for (int mt = 0; mt < 2; mt++) {
                mma_fp16(c[mt][0], af[mt], bf[0][0], bf[0][2]);
                mma_fp16(c[mt][1], af[mt], bf[0][1], bf[0][3]);
                mma_fp16(c[mt][2], af[mt], bf[1][0], bf[1][2]);
                mma_fp16(c[mt][3], af[mt], bf[1][1], bf[1][3]);
            }
        }

        // normalize -> p; stage fp16 p into Ps; write fp32 p to attn
        #pragma unroll
        for (int mt = 0; mt < 2; mt++) {
            const int r0 = wm * 32 + mt * 16 + gid;
            #pragma unroll
            for (int nt = 0; nt < 4; nt++) {
                const int cl = wn * 32 + nt * 8 + 2 * tig;
                float2 p0, p1;
                p0.x = ex2f(c[mt][nt][0] * EXS) * inv[mt][0];
                p0.y = ex2f(c[mt][nt][1] * EXS) * inv[mt][0];
                p1.x = ex2f(c[mt][nt][2] * EXS) * inv[mt][1];
                p1.y = ex2f(c[mt][nt][3] * EXS) * inv[mt][1];
                __half2 h0 = __floats2half2_rn(p0.x, p0.y);
                __half2 h1 = __floats2half2_rn(p1.x, p1.y);
                *(unsigned*)&Ps[r0 * PSP + cl]       = *(unsigned*)&h0;
                *(unsigned*)&Ps[(r0 + 8) * PSP + cl] = *(unsigned*)&h1;
                if (WRITE_ATTN) {
                    *(float2*)(attp + (size_t)r0 * SS + kt * 128 + cl)       = p0;
                    *(float2*)(attp + (size_t)(r0 + 8) * SS + kt * 128 + cl) = p1;
                }
            }
        }
        __syncthreads();

        // ctx += P @ V : A = Ps (64x128), B = Vs [kseq][d] via ldmatrix.trans
        #pragma unroll
        for (int kk = 0; kk < 128; kk += 16) {
            unsigned af[2][4], bf[4];
            ldsm4(af[0], PsU + ((wm * 32 + arow) * PSP + kk + acolh) * 2);
            ldsm4(af[1], PsU + ((wm * 32 + 16 + arow) * PSP + kk + acolh) * 2);
            ldsm4t(bf, VsU + ((kk + arow) * VSP + wn * 16 + acolh) * 2);
            #pragma unroll
            for (int mt = 0; mt < 2; mt++) {
                mma_fp16(cacc[mt][0], af[mt], bf[0], bf[1]);
                mma_fp16(cacc[mt][1], af[mt], bf[2], bf[3]);
            }
        }
    }

    float* cp = ctx + base + (size_t)q0 * DD;
    #pragma unroll
    for (int mt = 0; mt < 2; mt++) {
        const int r0 = wm * 32 + mt * 16 + gid;
        #pragma unroll
        for (int nt = 0; nt < 2; nt++) {
            const int cl = wn * 16 + nt * 8 + 2 * tig;
            *(float2*)(cp + (size_t)r0 * DD + cl)       = make_float2(cacc[mt][nt][0], cacc[mt][nt][1]);
            *(float2*)(cp + (size_t)(r0 + 8) * DD + cl) = make_float2(cacc[mt][nt][2], cacc[mt][nt][3]);
        }
    }
}

// ---------------------------------------------------------------------------
// Projection GEMM: C = A @ B^T (fp16 MMA), 128x128x64 tile, 256 threads.
// ---------------------------------------------------------------------------
#define GSP 72

__global__ __launch_bounds__(256, 2) void gemm_tc(
    const float* __restrict__ A, const float* __restrict__ Bm, float* __restrict__ C)
{
    __shared__ __half As[128 * GSP];
    __shared__ __half Bs[128 * GSP];

    const unsigned AsU = (unsigned)__cvta_generic_to_shared(As);
    const unsigned BsU = (unsigned)__cvta_generic_to_shared(Bs);

    const int tid = threadIdx.x;
    const int warp = tid >> 5, l = tid & 31;
    const int gid = l >> 2, tig = l & 3;
    const int wm = warp >> 1, wn = warp & 1;  // 4 x 2
    const int m0 = blockIdx.y * 128;
    const int n0 = blockIdx.x * 128;

    const int arow  = (l & 7) + ((l >> 3) & 1) * 8;
    const int acolh = (l >> 4) * 8;

    const int lr = tid >> 1;
    const int lc = (tid & 1) * 32;

    float acc[2][8][4] = {};

    for (int k0 = 0; k0 < DD; k0 += 64) {
        #pragma unroll
        for (int i = 0; i < 8; i++) {
            const float4 a4 = *(const float4*)(A + (size_t)(m0 + lr) * DD + k0 + lc + i * 4);
            st_h4(&As[lr * GSP + lc + i * 4], a4);
            const float4 b4 = *(const float4*)(Bm + (size_t)(n0 + lr) * DD + k0 + lc + i * 4);
            st_h4(&Bs[lr * GSP + lc + i * 4], b4);
        }
        __syncthreads();

        #pragma unroll
        for (int kk = 0; kk < 64; kk += 16) {
            unsigned af[2][4], bf[4][4];
            ldsm4(af[0], AsU + ((wm * 32 + arow) * GSP + kk + acolh) * 2);
            ldsm4(af[1], AsU + ((wm * 32 + 16 + arow) * GSP + kk + acolh) * 2);
            #pragma unroll
            for (int p = 0; p < 4; p++)
                ldsm4(bf[p], BsU + ((wn * 64 + p * 16 + arow) * GSP + kk + acolh) * 2);
            #pragma unroll
            for (int mt = 0; mt < 2; mt++)
                #pragma unroll
                for (int p = 0; p < 4; p++) {
                    mma_fp16(acc[mt][p * 2],     af[mt], bf[p][0], bf[p][2]);
                    mma_fp16(acc[mt][p * 2 + 1], af[mt], bf[p][1], bf[p][3]);
                }
        }
        __syncthreads();
    }

    #pragma unroll
    for (int mt = 0; mt < 2; mt++) {
        #pragma unroll
        for (int nt = 0; nt < 8; nt++) {
            const int r0 = m0 + wm * 32 + mt * 16 + gid;
            const int cc = n0 + wn * 64 + nt * 8 + tig * 2;
            *(float2*)(C + (size_t)r0 * DD + cc)       = make_float2(acc[mt][nt][0], acc[mt][nt][1]);
            *(float2*)(C + (size_t)(r0 + 8) * DD + cc) = make_float2(acc[mt][nt][2], acc[mt][nt][3]);
        }
    }
}

// ---------------------------------------------------------------------------
// Fused bias + residual + LayerNorm.
// ---------------------------------------------------------------------------
__global__ __launch_bounds__(256) void ln_kernel(
    const float* __restrict__ po, const float* __restrict__ x,
    const float* __restrict__ bo, const float* __restrict__ gamma,
    const float* __restrict__ beta, float* __restrict__ y)
{
    const size_t row = blockIdx.x;
    const float* pr = po + row * DD;
    const float* xr = x + row * DD;
    float* yr = y + row * DD;
    const int t = threadIdx.x;

    float tv[4];
    float s = 0.f, s2 = 0.f;
    #pragma unroll
    for (int i = 0; i < 4; i++) {
        const int c = t + i * 256;
        const float u = pr[c] + bo[c] + xr[c];
        tv[i] = u;
        s += u;
        s2 += u * u;
    }

    __shared__ float r1[8], r2[8];
    #pragma unroll
    for (int o = 16; o; o >>= 1) {
        s  += __shfl_xor_sync(0xffffffffu, s, o);
        s2 += __shfl_xor_sync(0xffffffffu, s2, o);
    }
    if ((t & 31) == 0) { r1[t >> 5] = s; r2[t >> 5] = s2; }
    __syncthreads();
    s = r1[0]; s2 = r2[0];
    #pragma unroll
    for (int i = 1; i < 8; i++) { s += r1[i]; s2 += r2[i]; }

    const float mu = s * (1.0f / DD);
    const float var = s2 * (1.0f / DD) - mu * mu;
    const float inv = rsqrtf(var + 1e-5f);

    #pragma unroll
    for (int i = 0; i < 4; i++) {
        const int c = t + i * 256;
        yr[c] = (tv[i] - mu) * inv * gamma[c] + beta[c];
    }
}

// ---------------------------------------------------------------------------
extern "C" void kernel_launch(void* const* d_in, const int* in_sizes, int n_in,
                              void* d_out, int out_size)
{
    const float* x     = (const float*)d_in[0];
    const float* Wq    = (const float*)d_in[1];
    const float* Wk    = (const float*)d_in[2];
    const float* Wv    = (const float*)d_in[3];
    const float* Wo    = (const float*)d_in[4];
    const float* bo    = (const float*)d_in[5];
    const float* gamma = (const float*)d_in[6];
    const float* beta  = (const float*)d_in[7];

    float *q, *k, *v, *ctx, *po, *attn_scratch;
    cudaGetSymbolAddress((void**)&q,   g_q);
    cudaGetSymbolAddress((void**)&k,   g_k);
    cudaGetSymbolAddress((void**)&v,   g_v);
    cudaGetSymbolAddress((void**)&ctx, g_ctx);
    cudaGetSymbolAddress((void**)&po,  g_po);
    cudaGetSymbolAddress((void**)&attn_scratch, g_attn);

    const size_t Y   = (size_t)BB * SS * DD;
    const size_t ATT = (size_t)BB * HH * SS * SS;

    float* yout = (float*)d_out;
    const bool want_attn = ((size_t)out_size >= Y + ATT);
    float* attn = want_attn ? (yout + Y) : attn_scratch;

    const dim3 blk(256);

    // Q/K/V projections
    const dim3 gproj(DD / 128, (BB * SS) / 128, 1);
    gemm_tc<<<gproj, blk>>>(x, Wq, q);
    gemm_tc<<<gproj, blk>>>(x, Wk, k);
    gemm_tc<<<gproj, blk>>>(x, Wv, v);

    // fused attention
    const dim3 gatt(SS / 64, BB * HH);
    if (want_attn) {
        cudaFuncSetAttribute(attn_kernel<true>, cudaFuncAttributeMaxDynamicSharedMemorySize, SM_BYTES);
        attn_kernel<true><<<gatt, 256, SM_BYTES>>>(q, k, v, attn, ctx);
    } else {
        cudaFuncSetAttribute(attn_kernel<false>, cudaFuncAttributeMaxDynamicSharedMemorySize, SM_BYTES);
        attn_kernel<false><<<gatt, 256, SM_BYTES>>>(q, k, v, attn, ctx);
    }

    // output projection
    gemm_tc<<<gproj, blk>>>(ctx, Wo, po);

    // bias + residual + LayerNorm -> y
    ln_kernel<<<BB * SS, blk>>>(po, x, bo, gamma, beta, yout);
}

// round 8
// speedup vs baseline: 1.6589x; 1.6589x over previous
#include <cuda_runtime.h>
#include <cuda_fp16.h>

#define BB 2
#define SS 2048
#define DD 1024
#define HH 16
#define DK 64

// Scratch (allocation-free: __device__ globals). q/k/v/ctx stored fp16.
__device__ __half g_q[(size_t)BB * SS * DD];
__device__ __half g_k[(size_t)BB * SS * DD];
__device__ __half g_v[(size_t)BB * SS * DD];
__device__ __half g_ctx[(size_t)BB * SS * DD];
__device__ float  g_po[(size_t)BB * SS * DD];
__device__ float  g_attn[(size_t)BB * HH * SS * SS];

__device__ __forceinline__ float ex2f(float x) {
    float y;
    asm("ex2.approx.ftz.f32 %0, %1;" : "=f"(y) : "f"(x));
    return y;
}

__device__ __forceinline__ void mma_fp16(float* c, const unsigned* a, unsigned b0, unsigned b1) {
    asm volatile(
        "mma.sync.aligned.m16n8k16.row.col.f32.f16.f16.f32 "
        "{%0,%1,%2,%3}, {%4,%5,%6,%7}, {%8,%9}, {%0,%1,%2,%3};\n"
        : "+f"(c[0]), "+f"(c[1]), "+f"(c[2]), "+f"(c[3])
        : "r"(a[0]), "r"(a[1]), "r"(a[2]), "r"(a[3]), "r"(b0), "r"(b1));
}

__device__ __forceinline__ void ldsm4(unsigned* r, unsigned addr) {
    asm volatile("ldmatrix.sync.aligned.m8n8.x4.shared.b16 {%0,%1,%2,%3}, [%4];"
                 : "=r"(r[0]), "=r"(r[1]), "=r"(r[2]), "=r"(r[3]) : "r"(addr));
}

__device__ __forceinline__ void ldsm4t(unsigned* r, unsigned addr) {
    asm volatile("ldmatrix.sync.aligned.m8n8.x4.trans.shared.b16 {%0,%1,%2,%3}, [%4];"
                 : "=r"(r[0]), "=r"(r[1]), "=r"(r[2]), "=r"(r[3]) : "r"(addr));
}

__device__ __forceinline__ void st_h4(__half* dst, float4 v) {
    __half2 h0 = __floats2half2_rn(v.x, v.y);
    __half2 h1 = __floats2half2_rn(v.z, v.w);
    *(uint2*)dst = make_uint2(*(unsigned*)&h0, *(unsigned*)&h1);
}

#define CP_A16(dst, src) asm volatile("cp.async.cg.shared.global [%0], [%1], 16;\n" :: "r"(dst), "l"(src))
#define CP_COMMIT()      asm volatile("cp.async.commit_group;\n")
#define CP_WAIT1()       asm volatile("cp.async.wait_group 1;\n")
#define CP_WAIT0()       asm volatile("cp.async.wait_group 0;\n")

#define EXS 0.18033688f  /* 0.125 * log2(e) */

// strides in halves; stride*2 mod 128 == 16 -> conflict-free ldmatrix rows,
// and stride*2 % 16 == 0 -> cp.async 16B-aligned rows.
#define QSP 72
#define KSP 72
#define VSP 72
#define PSP 136

#define SM_QS 0
#define SM_K0 4608              /* 64*72 */
#define KTILE 9216              /* 128*72 halves per K buffer */
#define SM_V0 (SM_K0 + 2 * KTILE)
#define SM_PS (SM_V0 + 2 * KTILE)
#define SM_ENDH (SM_PS + 64 * PSP)
#define SM_BYTES (SM_ENDH * 2 + 64 * 4)   /* + rs[64] = 100,608 B */

// ---------------------------------------------------------------------------
// Fused attention, fp16 in/out, cp.async double-buffered K/V tiles.
// 64 q rows per CTA, 256 threads (8 warps 2x4), 2 CTAs/SM.
// ---------------------------------------------------------------------------
template <bool WRITE_ATTN>
__global__ __launch_bounds__(256, 2) void attn_kernel(
    const __half* __restrict__ q, const __half* __restrict__ k,
    const __half* __restrict__ v, float* __restrict__ attn,
    __half* __restrict__ ctx)
{
    extern __shared__ __half smh[];
    __half* Ps = smh + SM_PS;
    float* rs  = (float*)(smh + SM_ENDH);

    const unsigned smu = (unsigned)__cvta_generic_to_shared(smh);
    const unsigned QsU = smu + SM_QS * 2;
    const unsigned KsU = smu + SM_K0 * 2;
    const unsigned VsU = smu + SM_V0 * 2;
    const unsigned PsU = smu + SM_PS * 2;

    const int z = blockIdx.y;
    const int b = z >> 4, h = z & 15;
    const size_t base = (size_t)b * SS * DD + (size_t)h * DK;
    const int q0 = blockIdx.x * 64;

    const __half* qp = q + base + (size_t)q0 * DD;
    const __half* kp = k + base;
    const __half* vp = v + base;
    float* attp = attn + (size_t)z * SS * SS + (size_t)q0 * SS;

    const int tid = threadIdx.x;
    const int warp = tid >> 5, l = tid & 31;
    const int gid = l >> 2, tig = l & 3;
    const int wm = warp >> 2, wn = warp & 3;   // 2 x 4

    const int arow  = (l & 7) + ((l >> 3) & 1) * 8;
    const int acolh = (l >> 4) * 8;

    // cp.async chunk mapping: idx -> row = idx>>3, 16B chunk = idx&7
    const int crow0 = tid >> 3, cch = (tid & 7) * 8;  // halves offset within row

    // ---- prefetch Q (64 rows) + K tile 0 ----
    #pragma unroll
    for (int i = 0; i < 2; i++) {
        const int row = crow0 + i * 32;
        CP_A16(QsU + (row * QSP + cch) * 2, qp + (size_t)row * DD + cch);
    }
    #pragma unroll
    for (int i = 0; i < 4; i++) {
        const int row = crow0 + i * 32;
        CP_A16(KsU + (row * KSP + cch) * 2, kp + (size_t)row * DD + cch);
    }
    CP_COMMIT();
    if (tid < 64) rs[tid] = 0.f;

    float rsum[2][2] = {};

    // =================== PASS 1: row sums ===================
    for (int kt = 0; kt < SS / 128; kt++) {
        if (kt < 15) {
            const unsigned kb = KsU + ((kt + 1) & 1) * KTILE * 2;
            #pragma unroll
            for (int i = 0; i < 4; i++) {
                const int row = crow0 + i * 32;
                CP_A16(kb + (row * KSP + cch) * 2, kp + (size_t)((kt + 1) * 128 + row) * DD + cch);
            }
            CP_COMMIT();
            CP_WAIT1();
        } else {
            CP_WAIT0();
        }
        __syncthreads();

        const unsigned kcur = KsU + (kt & 1) * KTILE * 2;
        float c[2][4][4] = {};
        #pragma unroll
        for (int kk = 0; kk < DK; kk += 16) {
            unsigned af[2][4], bf[2][4];
            ldsm4(af[0], QsU + ((wm * 32 + arow) * QSP + kk + acolh) * 2);
            ldsm4(af[1], QsU + ((wm * 32 + 16 + arow) * QSP + kk + acolh) * 2);
            ldsm4(bf[0], kcur + ((wn * 32 + arow) * KSP + kk + acolh) * 2);
            ldsm4(bf[1], kcur + ((wn * 32 + 16 + arow) * KSP + kk + acolh) * 2);
            #pragma unroll
            for (int mt = 0; mt < 2; mt++) {
                mma_fp16(c[mt][0], af[mt], bf[0][0], bf[0][2]);
                mma_fp16(c[mt][1], af[mt], bf[0][1], bf[0][3]);
                mma_fp16(c[mt][2], af[mt], bf[1][0], bf[1][2]);
                mma_fp16(c[mt][3], af[mt], bf[1][1], bf[1][3]);
            }
        }
        #pragma unroll
        for (int mt = 0; mt < 2; mt++)
            #pragma unroll
            for (int nt = 0; nt < 4; nt++) {
                rsum[mt][0] += ex2f(c[mt][nt][0] * EXS) + ex2f(c[mt][nt][1] * EXS);
                rsum[mt][1] += ex2f(c[mt][nt][2] * EXS) + ex2f(c[mt][nt][3] * EXS);
            }
        __syncthreads();
    }

    #pragma unroll
    for (int mt = 0; mt < 2; mt++)
        #pragma unroll
        for (int hf = 0; hf < 2; hf++) {
            float v0 = rsum[mt][hf];
            v0 += __shfl_xor_sync(0xffffffffu, v0, 1);
            v0 += __shfl_xor_sync(0xffffffffu, v0, 2);
            if (tig == 0) atomicAdd(&rs[wm * 32 + mt * 16 + hf * 8 + gid], v0);
        }
    __syncthreads();

    float inv[2][2];
    #pragma unroll
    for (int mt = 0; mt < 2; mt++)
        #pragma unroll
        for (int hf = 0; hf < 2; hf++)
            inv[mt][hf] = 1.0f / rs[wm * 32 + mt * 16 + hf * 8 + gid];

    float cacc[2][2][4] = {};

    // ---- prefetch K+V tile 0 for pass 2 ----
    #pragma unroll
    for (int i = 0; i < 4; i++) {
        const int row = crow0 + i * 32;
        CP_A16(KsU + (row * KSP + cch) * 2, kp + (size_t)row * DD + cch);
        CP_A16(VsU + (row * VSP + cch) * 2, vp + (size_t)row * DD + cch);
    }
    CP_COMMIT();

    // =================== PASS 2 ===================
    for (int kt = 0; kt < SS / 128; kt++) {
        if (kt < 15) {
            const unsigned kb = KsU + ((kt + 1) & 1) * KTILE * 2;
            const unsigned vb = VsU + ((kt + 1) & 1) * KTILE * 2;
            #pragma unroll
            for (int i = 0; i < 4; i++) {
                const int row = crow0 + i * 32;
                CP_A16(kb + (row * KSP + cch) * 2, kp + (size_t)((kt + 1) * 128 + row) * DD + cch);
                CP_A16(vb + (row * VSP + cch) * 2, vp + (size_t)((kt + 1) * 128 + row) * DD + cch);
            }
            CP_COMMIT();
            CP_WAIT1();
        } else {
            CP_WAIT0();
        }
        __syncthreads();

        const unsigned kcur = KsU + (kt & 1) * KTILE * 2;
        const unsigned vcur = VsU + (kt & 1) * KTILE * 2;

        float c[2][4][4] = {};
        #pragma unroll
        for (int kk = 0; kk < DK; kk += 16) {
            unsigned af[2][4], bf[2][4];
            ldsm4(af[0], QsU + ((wm * 32 + arow) * QSP + kk + acolh) * 2);
            ldsm4(af[1], QsU + ((wm * 32 + 16 + arow) * QSP + kk + acolh) * 2);
            ldsm4(bf[0], kcur + ((wn * 32 + arow) * KSP + kk + acolh) * 2);
            ldsm4(bf[1], kcur + ((wn * 32 + 16 + arow) * KSP + kk + acolh) * 2);
            #pragma unroll
            for (int mt = 0; mt < 2; mt++) {
                mma_fp16(c[mt][0], af[mt], bf[0][0], bf[0][2]);
                mma_fp16(c[mt][1], af[mt], bf[0][1], bf[0][3]);
                mma_fp16(c[mt][2], af[mt], bf[1][0], bf[1][2]);
                mma_fp16(c[mt][3], af[mt], bf[1][1], bf[1][3]);
            }
        }

        // normalize -> fp16 P staged in smem
        #pragma unroll
        for (int mt = 0; mt < 2; mt++) {
            const int r0 = wm * 32 + mt * 16 + gid;
            #pragma unroll
            for (int nt = 0; nt < 4; nt++) {
                const int cl = wn * 32 + nt * 8 + 2 * tig;
                __half2 h0 = __floats2half2_rn(ex2f(c[mt][nt][0] * EXS) * inv[mt][0],
                                               ex2f(c[mt][nt][1] * EXS) * inv[mt][0]);
                __half2 h1 = __floats2half2_rn(ex2f(c[mt][nt][2] * EXS) * inv[mt][1],
                                               ex2f(c[mt][nt][3] * EXS) * inv[mt][1]);
                *(unsigned*)&Ps[r0 * PSP + cl]       = *(unsigned*)&h0;
                *(unsigned*)&Ps[(r0 + 8) * PSP + cl] = *(unsigned*)&h1;
            }
        }
        __syncthreads();

        // ctx += P @ V
        #pragma unroll
        for (int kk = 0; kk < 128; kk += 16) {
            unsigned af[2][4], bf[4];
            ldsm4(af[0], PsU + ((wm * 32 + arow) * PSP + kk + acolh) * 2);
            ldsm4(af[1], PsU + ((wm * 32 + 16 + arow) * PSP + kk + acolh) * 2);
            ldsm4t(bf, vcur + ((kk + arow) * VSP + wn * 16 + acolh) * 2);
            #pragma unroll
            for (int mt = 0; mt < 2; mt++) {
                mma_fp16(cacc[mt][0], af[mt], bf[0], bf[1]);
                mma_fp16(cacc[mt][1], af[mt], bf[2], bf[3]);
            }
        }

        // coalesced attn copy-out from Ps: warp row = 128B contiguous STG.128
        if (WRITE_ATTN) {
            #pragma unroll
            for (int i = 0; i < 8; i++) {
                const int idx = tid + i * 256;
                const int row = idx >> 5, c4 = idx & 31;
                const uint2 hraw = *(const uint2*)&Ps[row * PSP + c4 * 4];
                const float2 f01 = __half22float2(*(const __half2*)&hraw.x);
                const float2 f23 = __half22float2(*(const __half2*)&hraw.y);
                *(float4*)(attp + (size_t)row * SS + kt * 128 + c4 * 4) =
                    make_float4(f01.x, f01.y, f23.x, f23.y);
            }
        }
        __syncthreads();
    }

    // ctx tile (64x64) -> fp16 gmem
    __half* cp = ctx + base + (size_t)q0 * DD;
    #pragma unroll
    for (int mt = 0; mt < 2; mt++) {
        const int r0 = wm * 32 + mt * 16 + gid;
        #pragma unroll
        for (int nt = 0; nt < 2; nt++) {
            const int cl = wn * 16 + nt * 8 + 2 * tig;
            __half2 h0 = __floats2half2_rn(cacc[mt][nt][0], cacc[mt][nt][1]);
            __half2 h1 = __floats2half2_rn(cacc[mt][nt][2], cacc[mt][nt][3]);
            *(unsigned*)(cp + (size_t)r0 * DD + cl)       = *(unsigned*)&h0;
            *(unsigned*)(cp + (size_t)(r0 + 8) * DD + cl) = *(unsigned*)&h1;
        }
    }
}

// ---------------------------------------------------------------------------
// Projection GEMM: C = A @ B^T (fp16 MMA), 128x128x64 tile, 256 threads.
// AH: A is fp16 in gmem. CH: C written fp16.
// ---------------------------------------------------------------------------
#define GSP 72

template <bool AH, bool CH>
__global__ __launch_bounds__(256, 2) void gemm_tc(
    const void* __restrict__ Ap, const float* __restrict__ Bm, void* __restrict__ Cp)
{
    __shared__ __half As[128 * GSP];
    __shared__ __half Bs[128 * GSP];

    const unsigned AsU = (unsigned)__cvta_generic_to_shared(As);
    const unsigned BsU = (unsigned)__cvta_generic_to_shared(Bs);

    const int tid = threadIdx.x;
    const int warp = tid >> 5, l = tid & 31;
    const int gid = l >> 2, tig = l & 3;
    const int wm = warp >> 1, wn = warp & 1;
    const int m0 = blockIdx.y * 128;
    const int n0 = blockIdx.x * 128;

    const int arow  = (l & 7) + ((l >> 3) & 1) * 8;
    const int acolh = (l >> 4) * 8;

    const int lr = tid >> 1;
    const int lc = (tid & 1) * 32;

    float acc[2][8][4] = {};

    for (int k0 = 0; k0 < DD; k0 += 64) {
        if (AH) {
            const __half* A = (const __half*)Ap;
            const int row = tid >> 3, ch = (tid & 7) * 8;
            #pragma unroll
            for (int i = 0; i < 4; i++) {
                const int r = row + i * 32;
                *(uint4*)&As[r * GSP + ch] = *(const uint4*)(A + (size_t)(m0 + r) * DD + k0 + ch);
            }
        } else {
            const float* A = (const float*)Ap;
            #pragma unroll
            for (int i = 0; i < 8; i++) {
                const float4 a4 = *(const float4*)(A + (size_t)(m0 + lr) * DD + k0 + lc + i * 4);
                st_h4(&As[lr * GSP + lc + i * 4], a4);
            }
        }
        #pragma unroll
        for (int i = 0; i < 8; i++) {
            const float4 b4 = *(const float4*)(Bm + (size_t)(n0 + lr) * DD + k0 + lc + i * 4);
            st_h4(&Bs[lr * GSP + lc + i * 4], b4);
        }
        __syncthreads();

        #pragma unroll
        for (int kk = 0; kk < 64; kk += 16) {
            unsigned af[2][4], bf[4][4];
            ldsm4(af[0], AsU + ((wm * 32 + arow) * GSP + kk + acolh) * 2);
            ldsm4(af[1], AsU + ((wm * 32 + 16 + arow) * GSP + kk + acolh) * 2);
            #pragma unroll
            for (int p = 0; p < 4; p++)
                ldsm4(bf[p], BsU + ((wn * 64 + p * 16 + arow) * GSP + kk + acolh) * 2);
            #pragma unroll
            for (int mt = 0; mt < 2; mt++)
                #pragma unroll
                for (int p = 0; p < 4; p++) {
                    mma_fp16(acc[mt][p * 2],     af[mt], bf[p][0], bf[p][2]);
                    mma_fp16(acc[mt][p * 2 + 1], af[mt], bf[p][1], bf[p][3]);
                }
        }
        __syncthreads();
    }

    #pragma unroll
    for (int mt = 0; mt < 2; mt++) {
        #pragma unroll
        for (int nt = 0; nt < 8; nt++) {
            const int r0 = m0 + wm * 32 + mt * 16 + gid;
            const int cc = n0 + wn * 64 + nt * 8 + tig * 2;
            if (CH) {
                __half* C = (__half*)Cp;
                __half2 h0 = __floats2half2_rn(acc[mt][nt][0], acc[mt][nt][1]);
                __half2 h1 = __floats2half2_rn(acc[mt][nt][2], acc[mt][nt][3]);
                *(unsigned*)(C + (size_t)r0 * DD + cc)       = *(unsigned*)&h0;
                *(unsigned*)(C + (size_t)(r0 + 8) * DD + cc) = *(unsigned*)&h1;
            } else {
                float* C = (float*)Cp;
                *(float2*)(C + (size_t)r0 * DD + cc)       = make_float2(acc[mt][nt][0], acc[mt][nt][1]);
                *(float2*)(C + (size_t)(r0 + 8) * DD + cc) = make_float2(acc[mt][nt][2], acc[mt][nt][3]);
            }
        }
    }
}

// ---------------------------------------------------------------------------
// Fused bias + residual + LayerNorm.
// ---------------------------------------------------------------------------
__global__ __launch_bounds__(256) void ln_kernel(
    const float* __restrict__ po, const float* __restrict__ x,
    const float* __restrict__ bo, const float* __restrict__ gamma,
    const float* __restrict__ beta, float* __restrict__ y)
{
    const size_t row = blockIdx.x;
    const float* pr = po + row * DD;
    const float* xr = x + row * DD;
    float* yr = y + row * DD;
    const int t = threadIdx.x;

    float tv[4];
    float s = 0.f, s2 = 0.f;
    #pragma unroll
    for (int i = 0; i < 4; i++) {
        const int c = t + i * 256;
        const float u = pr[c] + bo[c] + xr[c];
        tv[i] = u;
        s += u;
        s2 += u * u;
    }

    __shared__ float r1[8], r2[8];
    #pragma unroll
    for (int o = 16; o; o >>= 1) {
        s  += __shfl_xor_sync(0xffffffffu, s, o);
        s2 += __shfl_xor_sync(0xffffffffu, s2, o);
    }
    if ((t & 31) == 0) { r1[t >> 5] = s; r2[t >> 5] = s2; }
    __syncthreads();
    s = r1[0]; s2 = r2[0];
    #pragma unroll
    for (int i = 1; i < 8; i++) { s += r1[i]; s2 += r2[i]; }

    const float mu = s * (1.0f / DD);
    const float var = s2 * (1.0f / DD) - mu * mu;
    const float inv = rsqrtf(var + 1e-5f);

    #pragma unroll
    for (int i = 0; i < 4; i++) {
        const int c = t + i * 256;
        yr[c] = (tv[i] - mu) * inv * gamma[c] + beta[c];
    }
}

// ---------------------------------------------------------------------------
extern "C" void kernel_launch(void* const* d_in, const int* in_sizes, int n_in,
                              void* d_out, int out_size)
{
    const float* x     = (const float*)d_in[0];
    const float* Wq    = (const float*)d_in[1];
    const float* Wk    = (const float*)d_in[2];
    const float* Wv    = (const float*)d_in[3];
    const float* Wo    = (const float*)d_in[4];
    const float* bo    = (const float*)d_in[5];
    const float* gamma = (const float*)d_in[6];
    const float* beta  = (const float*)d_in[7];

    __half *q, *k, *v, *ctx;
    float *po, *attn_scratch;
    cudaGetSymbolAddress((void**)&q,   g_q);
    cudaGetSymbolAddress((void**)&k,   g_k);
    cudaGetSymbolAddress((void**)&v,   g_v);
    cudaGetSymbolAddress((void**)&ctx, g_ctx);
    cudaGetSymbolAddress((void**)&po,  g_po);
    cudaGetSymbolAddress((void**)&attn_scratch, g_attn);

    const size_t Y   = (size_t)BB * SS * DD;
    const size_t ATT = (size_t)BB * HH * SS * SS;

    float* yout = (float*)d_out;
    const bool want_attn = ((size_t)out_size >= Y + ATT);
    float* attn = want_attn ? (yout + Y) : attn_scratch;

    const dim3 blk(256);

    // Q/K/V projections (fp32 in, fp16 out)
    const dim3 gproj(DD / 128, (BB * SS) / 128, 1);
    gemm_tc<false, true><<<gproj, blk>>>(x, Wq, q);
    gemm_tc<false, true><<<gproj, blk>>>(x, Wk, k);
    gemm_tc<false, true><<<gproj, blk>>>(x, Wv, v);

    // fused attention
    const dim3 gatt(SS / 64, BB * HH);
    if (want_attn) {
        cudaFuncSetAttribute(attn_kernel<true>, cudaFuncAttributeMaxDynamicSharedMemorySize, SM_BYTES);
        attn_kernel<true><<<gatt, 256, SM_BYTES>>>(q, k, v, attn, ctx);
    } else {
        cudaFuncSetAttribute(attn_kernel<false>, cudaFuncAttributeMaxDynamicSharedMemorySize, SM_BYTES);
        attn_kernel<false><<<gatt, 256, SM_BYTES>>>(q, k, v, attn, ctx);
    }

    // output projection (fp16 A in, fp32 out)
    gemm_tc<true, false><<<gproj, blk>>>(ctx, Wo, po);

    // bias + residual + LayerNorm -> y
    ln_kernel<<<BB * SS, blk>>>(po, x, bo, gamma, beta, yout);
}

// round 10
// speedup vs baseline: 2.4372x; 1.4692x over previous
#include <cuda_runtime.h>
#include <cuda_fp16.h>

#define BB 2
#define SS 2048
#define DD 1024
#define HH 16
#define DK 64

// Scratch (allocation-free: __device__ globals)
__device__ __half g_xh[(size_t)BB * SS * DD];
__device__ __half g_wh[4 * (size_t)DD * DD];   // Wq,Wk,Wv,Wo fp16
__device__ __half g_q[(size_t)BB * SS * DD];
__device__ __half g_k[(size_t)BB * SS * DD];
__device__ __half g_v[(size_t)BB * SS * DD];
__device__ __half g_ctx[(size_t)BB * SS * DD];
__device__ float  g_po[(size_t)BB * SS * DD];
__device__ float  g_attn[(size_t)BB * HH * SS * SS];

__device__ __forceinline__ float ex2f(float x) {
    float y;
    asm("ex2.approx.ftz.f32 %0, %1;" : "=f"(y) : "f"(x));
    return y;
}

__device__ __forceinline__ void mma_fp16(float* c, const unsigned* a, unsigned b0, unsigned b1) {
    asm volatile(
        "mma.sync.aligned.m16n8k16.row.col.f32.f16.f16.f32 "
        "{%0,%1,%2,%3}, {%4,%5,%6,%7}, {%8,%9}, {%0,%1,%2,%3};\n"
        : "+f"(c[0]), "+f"(c[1]), "+f"(c[2]), "+f"(c[3])
        : "r"(a[0]), "r"(a[1]), "r"(a[2]), "r"(a[3]), "r"(b0), "r"(b1));
}

__device__ __forceinline__ void ldsm4(unsigned* r, unsigned addr) {
    asm volatile("ldmatrix.sync.aligned.m8n8.x4.shared.b16 {%0,%1,%2,%3}, [%4];"
                 : "=r"(r[0]), "=r"(r[1]), "=r"(r[2]), "=r"(r[3]) : "r"(addr));
}

__device__ __forceinline__ void ldsm4t(unsigned* r, unsigned addr) {
    asm volatile("ldmatrix.sync.aligned.m8n8.x4.trans.shared.b16 {%0,%1,%2,%3}, [%4];"
                 : "=r"(r[0]), "=r"(r[1]), "=r"(r[2]), "=r"(r[3]) : "r"(addr));
}

#define CP_A16(dst, src) asm volatile("cp.async.cg.shared.global [%0], [%1], 16;\n" :: "r"(dst), "l"(src))
#define CP_COMMIT()      asm volatile("cp.async.commit_group;\n")
#define CP_WAIT1()       asm volatile("cp.async.wait_group 1;\n")
#define CP_WAIT0()       asm volatile("cp.async.wait_group 0;\n")

#define EXS 0.18033688f  /* 0.125 * log2(e) */

// ---------------------------------------------------------------------------
// fp32 -> fp16 streaming convert (vectorized)
// ---------------------------------------------------------------------------
__global__ __launch_bounds__(256) void f2h_kernel(const float4* __restrict__ in,
                                                  uint2* __restrict__ out, int n4)
{
    const int i = blockIdx.x * 256 + threadIdx.x;
    if (i < n4) {
        const float4 v = in[i];
        __half2 h0 = __floats2half2_rn(v.x, v.y);
        __half2 h1 = __floats2half2_rn(v.z, v.w);
        out[i] = make_uint2(*(unsigned*)&h0, *(unsigned*)&h1);
    }
}

// ===========================================================================
// Attention kernel (unchanged from R8 winner)
// ===========================================================================
#define QSP 72
#define KSP 72
#define VSP 72
#define PSP 136

#define SM_QS 0
#define SM_K0 4608
#define KTILE 9216
#define SM_V0 (SM_K0 + 2 * KTILE)
#define SM_PS (SM_V0 + 2 * KTILE)
#define SM_ENDH (SM_PS + 64 * PSP)
#define SM_BYTES (SM_ENDH * 2 + 64 * 4)

template <bool WRITE_ATTN>
__global__ __launch_bounds__(256, 2) void attn_kernel(
    const __half* __restrict__ q, const __half* __restrict__ k,
    const __half* __restrict__ v, float* __restrict__ attn,
    __half* __restrict__ ctx)
{
    extern __shared__ __half smh[];
    __half* Ps = smh + SM_PS;
    float* rs  = (float*)(smh + SM_ENDH);

    const unsigned smu = (unsigned)__cvta_generic_to_shared(smh);
    const unsigned QsU = smu + SM_QS * 2;
    const unsigned KsU = smu + SM_K0 * 2;
    const unsigned VsU = smu + SM_V0 * 2;
    const unsigned PsU = smu + SM_PS * 2;

    const int z = blockIdx.y;
    const int b = z >> 4, h = z & 15;
    const size_t base = (size_t)b * SS * DD + (size_t)h * DK;
    const int q0 = blockIdx.x * 64;

    const __half* qp = q + base + (size_t)q0 * DD;
    const __half* kp = k + base;
    const __half* vp = v + base;
    float* attp = attn + (size_t)z * SS * SS + (size_t)q0 * SS;

    const int tid = threadIdx.x;
    const int warp = tid >> 5, l = tid & 31;
    const int gid = l >> 2, tig = l & 3;
    const int wm = warp >> 2, wn = warp & 3;

    const int arow  = (l & 7) + ((l >> 3) & 1) * 8;
    const int acolh = (l >> 4) * 8;

    const int crow0 = tid >> 3, cch = (tid & 7) * 8;

    #pragma unroll
    for (int i = 0; i < 2; i++) {
        const int row = crow0 + i * 32;
        CP_A16(QsU + (row * QSP + cch) * 2, qp + (size_t)row * DD + cch);
    }
    #pragma unroll
    for (int i = 0; i < 4; i++) {
        const int row = crow0 + i * 32;
        CP_A16(KsU + (row * KSP + cch) * 2, kp + (size_t)row * DD + cch);
    }
    CP_COMMIT();
    if (tid < 64) rs[tid] = 0.f;

    float rsum[2][2] = {};

    for (int kt = 0; kt < SS / 128; kt++) {
        if (kt < 15) {
            const unsigned kb = KsU + ((kt + 1) & 1) * KTILE * 2;
            #pragma unroll
            for (int i = 0; i < 4; i++) {
                const int row = crow0 + i * 32;
                CP_A16(kb + (row * KSP + cch) * 2, kp + (size_t)((kt + 1) * 128 + row) * DD + cch);
            }
            CP_COMMIT();
            CP_WAIT1();
        } else {
            CP_WAIT0();
        }
        __syncthreads();

        const unsigned kcur = KsU + (kt & 1) * KTILE * 2;
        float c[2][4][4] = {};
        #pragma unroll
        for (int kk = 0; kk < DK; kk += 16) {
            unsigned af[2][4], bf[2][4];
            ldsm4(af[0], QsU + ((wm * 32 + arow) * QSP + kk + acolh) * 2);
            ldsm4(af[1], QsU + ((wm * 32 + 16 + arow) * QSP + kk + acolh) * 2);
            ldsm4(bf[0], kcur + ((wn * 32 + arow) * KSP + kk + acolh) * 2);
            ldsm4(bf[1], kcur + ((wn * 32 + 16 + arow) * KSP + kk + acolh) * 2);
            #pragma unroll
            for (int mt = 0; mt < 2; mt++) {
                mma_fp16(c[mt][0], af[mt], bf[0][0], bf[0][2]);
                mma_fp16(c[mt][1], af[mt], bf[0][1], bf[0][3]);
                mma_fp16(c[mt][2], af[mt], bf[1][0], bf[1][2]);
                mma_fp16(c[mt][3], af[mt], bf[1][1], bf[1][3]);
            }
        }
        #pragma unroll
        for (int mt = 0; mt < 2; mt++)
            #pragma unroll
            for (int nt = 0; nt < 4; nt++) {
                rsum[mt][0] += ex2f(c[mt][nt][0] * EXS) + ex2f(c[mt][nt][1] * EXS);
                rsum[mt][1] += ex2f(c[mt][nt][2] * EXS) + ex2f(c[mt][nt][3] * EXS);
            }
        __syncthreads();
    }

    #pragma unroll
    for (int mt = 0; mt < 2; mt++)
        #pragma unroll
        for (int hf = 0; hf < 2; hf++) {
            float v0 = rsum[mt][hf];
            v0 += __shfl_xor_sync(0xffffffffu, v0, 1);
            v0 += __shfl_xor_sync(0xffffffffu, v0, 2);
            if (tig == 0) atomicAdd(&rs[wm * 32 + mt * 16 + hf * 8 + gid], v0);
        }
    __syncthreads();

    float inv[2][2];
    #pragma unroll
    for (int mt = 0; mt < 2; mt++)
        #pragma unroll
        for (int hf = 0; hf < 2; hf++)
            inv[mt][hf] = 1.0f / rs[wm * 32 + mt * 16 + hf * 8 + gid];

    float cacc[2][2][4] = {};

    #pragma unroll
    for (int i = 0; i < 4; i++) {
        const int row = crow0 + i * 32;
        CP_A16(KsU + (row * KSP + cch) * 2, kp + (size_t)row * DD + cch);
        CP_A16(VsU + (row * VSP + cch) * 2, vp + (size_t)row * DD + cch);
    }
    CP_COMMIT();

    for (int kt = 0; kt < SS / 128; kt++) {
        if (kt < 15) {
            const unsigned kb = KsU + ((kt + 1) & 1) * KTILE * 2;
            const unsigned vb = VsU + ((kt + 1) & 1) * KTILE * 2;
            #pragma unroll
            for (int i = 0; i < 4; i++) {
                const int row = crow0 + i * 32;
                CP_A16(kb + (row * KSP + cch) * 2, kp + (size_t)((kt + 1) * 128 + row) * DD + cch);
                CP_A16(vb + (row * VSP + cch) * 2, vp + (size_t)((kt + 1) * 128 + row) * DD + cch);
            }
            CP_COMMIT();
            CP_WAIT1();
        } else {
            CP_WAIT0();
        }
        __syncthreads();

        const unsigned kcur = KsU + (kt & 1) * KTILE * 2;
        const unsigned vcur = VsU + (kt & 1) * KTILE * 2;

        float c[2][4][4] = {};
        #pragma unroll
        for (int kk = 0; kk < DK; kk += 16) {
            unsigned af[2][4], bf[2][4];
            ldsm4(af[0], QsU + ((wm * 32 + arow) * QSP + kk + acolh) * 2);
            ldsm4(af[1], QsU + ((wm * 32 + 16 + arow) * QSP + kk + acolh) * 2);
            ldsm4(bf[0], kcur + ((wn * 32 + arow) * KSP + kk + acolh) * 2);
            ldsm4(bf[1], kcur + ((wn * 32 + 16 + arow) * KSP + kk + acolh) * 2);
            #pragma unroll
            for (int mt = 0; mt < 2; mt++) {
                mma_fp16(c[mt][0], af[mt], bf[0][0], bf[0][2]);
                mma_fp16(c[mt][1], af[mt], bf[0][1], bf[0][3]);
                mma_fp16(c[mt][2], af[mt], bf[1][0], bf[1][2]);
                mma_fp16(c[mt][3], af[mt], bf[1][1], bf[1][3]);
            }
        }

        #pragma unroll
        for (int mt = 0; mt < 2; mt++) {
            const int r0 = wm * 32 + mt * 16 + gid;
            #pragma unroll
            for (int nt = 0; nt < 4; nt++) {
                const int cl = wn * 32 + nt * 8 + 2 * tig;
                __half2 h0 = __floats2half2_rn(ex2f(c[mt][nt][0] * EXS) * inv[mt][0],
                                               ex2f(c[mt][nt][1] * EXS) * inv[mt][0]);
                __half2 h1 = __floats2half2_rn(ex2f(c[mt][nt][2] * EXS) * inv[mt][1],
                                               ex2f(c[mt][nt][3] * EXS) * inv[mt][1]);
                *(unsigned*)&Ps[r0 * PSP + cl]       = *(unsigned*)&h0;
                *(unsigned*)&Ps[(r0 + 8) * PSP + cl] = *(unsigned*)&h1;
            }
        }
        __syncthreads();

        #pragma unroll
        for (int kk = 0; kk < 128; kk += 16) {
            unsigned af[2][4], bf[4];
            ldsm4(af[0], PsU + ((wm * 32 + arow) * PSP + kk + acolh) * 2);
            ldsm4(af[1], PsU + ((wm * 32 + 16 + arow) * PSP + kk + acolh) * 2);
            ldsm4t(bf, vcur + ((kk + arow) * VSP + wn * 16 + acolh) * 2);
            #pragma unroll
            for (int mt = 0; mt < 2; mt++) {
                mma_fp16(cacc[mt][0], af[mt], bf[0], bf[1]);
                mma_fp16(cacc[mt][1], af[mt], bf[2], bf[3]);
            }
        }

        if (WRITE_ATTN) {
            #pragma unroll
            for (int i = 0; i < 8; i++) {
                const int idx = tid + i * 256;
                const int row = idx >> 5, c4 = idx & 31;
                const uint2 hraw = *(const uint2*)&Ps[row * PSP + c4 * 4];
                const float2 f01 = __half22float2(*(const __half2*)&hraw.x);
                const float2 f23 = __half22float2(*(const __half2*)&hraw.y);
                *(float4*)(attp + (size_t)row * SS + kt * 128 + c4 * 4) =
                    make_float4(f01.x, f01.y, f23.x, f23.y);
            }
        }
        __syncthreads();
    }

    __half* cp = ctx + base + (size_t)q0 * DD;
    #pragma unroll
    for (int mt = 0; mt < 2; mt++) {
        const int r0 = wm * 32 + mt * 16 + gid;
        #pragma unroll
        for (int nt = 0; nt < 2; nt++) {
            const int cl = wn * 16 + nt * 8 + 2 * tig;
            __half2 h0 = __floats2half2_rn(cacc[mt][nt][0], cacc[mt][nt][1]);
            __half2 h1 = __floats2half2_rn(cacc[mt][nt][2], cacc[mt][nt][3]);
            *(unsigned*)(cp + (size_t)r0 * DD + cl)       = *(unsigned*)&h0;
            *(unsigned*)(cp + (size_t)(r0 + 8) * DD + cl) = *(unsigned*)&h1;
        }
    }
}

// ===========================================================================
// Projection GEMM, all-fp16 operands, cp.async double-buffered.
// C = A @ B^T, 128x128x64 tile, 256 threads (8 warps 4x2), 2 CTAs/SM.
// ===========================================================================
#define GSP 72
#define GTILE (128 * GSP)                       /* halves per buffer */
#define GEMM_SMEM_BYTES (4 * GTILE * 2)         /* A0,A1,B0,B1 = 73,728 B */

template <bool CH>
__global__ __launch_bounds__(256, 2) void gemm_h(
    const __half* __restrict__ A, const __half* __restrict__ Bm, void* __restrict__ Cp)
{
    extern __shared__ __half gsm[];
    const unsigned smu = (unsigned)__cvta_generic_to_shared(gsm);
    const unsigned AsU = smu;                      // A buffers at 0, GTILE
    const unsigned BsU = smu + 2 * GTILE * 2;      // B buffers follow

    const int tid = threadIdx.x;
    const int warp = tid >> 5, l = tid & 31;
    const int gid = l >> 2, tig = l & 3;
    const int wm = warp >> 1, wn = warp & 1;
    const int m0 = blockIdx.y * 128;
    const int n0 = blockIdx.x * 128;

    const int arow  = (l & 7) + ((l >> 3) & 1) * 8;
    const int acolh = (l >> 4) * 8;

    const int crow0 = tid >> 3, cch = (tid & 7) * 8;   // 32 rows, 8 chunks/row

    float acc[2][8][4] = {};

    // prefetch tile 0
    #pragma unroll
    for (int i = 0; i < 4; i++) {
        const int row = crow0 + i * 32;
        CP_A16(AsU + (row * GSP + cch) * 2, A  + (size_t)(m0 + row) * DD + cch);
        CP_A16(BsU + (row * GSP + cch) * 2, Bm + (size_t)(n0 + row) * DD + cch);
    }
    CP_COMMIT();

    for (int it = 0; it < DD / 64; it++) {
        if (it < DD / 64 - 1) {
            const unsigned ab = AsU + ((it + 1) & 1) * GTILE * 2;
            const unsigned bb = BsU + ((it + 1) & 1) * GTILE * 2;
            const int k0 = (it + 1) * 64;
            #pragma unroll
            for (int i = 0; i < 4; i++) {
                const int row = crow0 + i * 32;
                CP_A16(ab + (row * GSP + cch) * 2, A  + (size_t)(m0 + row) * DD + k0 + cch);
                CP_A16(bb + (row * GSP + cch) * 2, Bm + (size_t)(n0 + row) * DD + k0 + cch);
            }
            CP_COMMIT();
            CP_WAIT1();
        } else {
            CP_WAIT0();
        }
        __syncthreads();

        const unsigned acur = AsU + (it & 1) * GTILE * 2;
        const unsigned bcur = BsU + (it & 1) * GTILE * 2;

        #pragma unroll
        for (int kk = 0; kk < 64; kk += 16) {
            unsigned af[2][4], bf[4][4];
            ldsm4(af[0], acur + ((wm * 32 + arow) * GSP + kk + acolh) * 2);
            ldsm4(af[1], acur + ((wm * 32 + 16 + arow) * GSP + kk + acolh) * 2);
            #pragma unroll
            for (int p = 0; p < 4; p++)
                ldsm4(bf[p], bcur + ((wn * 64 + p * 16 + arow) * GSP + kk + acolh) * 2);
            #pragma unroll
            for (int mt = 0; mt < 2; mt++)
                #pragma unroll
                for (int p = 0; p < 4; p++) {
                    mma_fp16(acc[mt][p * 2],     af[mt], bf[p][0], bf[p][2]);
                    mma_fp16(acc[mt][p * 2 + 1], af[mt], bf[p][1], bf[p][3]);
                }
        }
        __syncthreads();
    }

    #pragma unroll
    for (int mt = 0; mt < 2; mt++) {
        #pragma unroll
        for (int nt = 0; nt < 8; nt++) {
            const int r0 = m0 + wm * 32 + mt * 16 + gid;
            const int cc = n0 + wn * 64 + nt * 8 + tig * 2;
            if (CH) {
                __half* C = (__half*)Cp;
                __half2 h0 = __floats2half2_rn(acc[mt][nt][0], acc[mt][nt][1]);
                __half2 h1 = __floats2half2_rn(acc[mt][nt][2], acc[mt][nt][3]);
                *(unsigned*)(C + (size_t)r0 * DD + cc)       = *(unsigned*)&h0;
                *(unsigned*)(C + (size_t)(r0 + 8) * DD + cc) = *(unsigned*)&h1;
            } else {
                float* C = (float*)Cp;
                *(float2*)(C + (size_t)r0 * DD + cc)       = make_float2(acc[mt][nt][0], acc[mt][nt][1]);
                *(float2*)(C + (size_t)(r0 + 8) * DD + cc) = make_float2(acc[mt][nt][2], acc[mt][nt][3]);
            }
        }
    }
}

// ---------------------------------------------------------------------------
// Fused bias + residual + LayerNorm.
// ---------------------------------------------------------------------------
__global__ __launch_bounds__(256) void ln_kernel(
    const float* __restrict__ po, const float* __restrict__ x,
    const float* __restrict__ bo, const float* __restrict__ gamma,
    const float* __restrict__ beta, float* __restrict__ y)
{
    const size_t row = blockIdx.x;
    const float* pr = po + row * DD;
    const float* xr = x + row * DD;
    float* yr = y + row * DD;
    const int t = threadIdx.x;

    float tv[4];
    float s = 0.f, s2 = 0.f;
    #pragma unroll
    for (int i = 0; i < 4; i++) {
        const int c = t + i * 256;
        const float u = pr[c] + bo[c] + xr[c];
        tv[i] = u;
        s += u;
        s2 += u * u;
    }

    __shared__ float r1[8], r2[8];
    #pragma unroll
    for (int o = 16; o; o >>= 1) {
        s  += __shfl_xor_sync(0xffffffffu, s, o);
        s2 += __shfl_xor_sync(0xffffffffu, s2, o);
    }
    if ((t & 31) == 0) { r1[t >> 5] = s; r2[t >> 5] = s2; }
    __syncthreads();
    s = r1[0]; s2 = r2[0];
    #pragma unroll
    for (int i = 1; i < 8; i++) { s += r1[i]; s2 += r2[i]; }

    const float mu = s * (1.0f / DD);
    const float var = s2 * (1.0f / DD) - mu * mu;
    const float inv = rsqrtf(var + 1e-5f);

    #pragma unroll
    for (int i = 0; i < 4; i++) {
        const int c = t + i * 256;
        yr[c] = (tv[i] - mu) * inv * gamma[c] + beta[c];
    }
}

// ---------------------------------------------------------------------------
extern "C" void kernel_launch(void* const* d_in, const int* in_sizes, int n_in,
                              void* d_out, int out_size)
{
    const float* x     = (const float*)d_in[0];
    const float* Wq    = (const float*)d_in[1];
    const float* Wk    = (const float*)d_in[2];
    const float* Wv    = (const float*)d_in[3];
    const float* Wo    = (const float*)d_in[4];
    const float* bo    = (const float*)d_in[5];
    const float* gamma = (const float*)d_in[6];
    const float* beta  = (const float*)d_in[7];

    __half *xh, *wh, *q, *k, *v, *ctx;
    float *po, *attn_scratch;
    cudaGetSymbolAddress((void**)&xh,  g_xh);
    cudaGetSymbolAddress((void**)&wh,  g_wh);
    cudaGetSymbolAddress((void**)&q,   g_q);
    cudaGetSymbolAddress((void**)&k,   g_k);
    cudaGetSymbolAddress((void**)&v,   g_v);
    cudaGetSymbolAddress((void**)&ctx, g_ctx);
    cudaGetSymbolAddress((void**)&po,  g_po);
    cudaGetSymbolAddress((void**)&attn_scratch, g_attn);

    const size_t Y   = (size_t)BB * SS * DD;
    const size_t ATT = (size_t)BB * HH * SS * SS;
    const size_t W   = (size_t)DD * DD;

    float* yout = (float*)d_out;
    const bool want_attn = ((size_t)out_size >= Y + ATT);
    float* attn = want_attn ? (yout + Y) : attn_scratch;

    const dim3 blk(256);

    // fp32 -> fp16 conversions (x and all weights)
    f2h_kernel<<<(int)(Y / 4 + 255) / 256, blk>>>((const float4*)x, (uint2*)xh, (int)(Y / 4));
    f2h_kernel<<<(int)(W / 4 + 255) / 256, blk>>>((const float4*)Wq, (uint2*)(wh + 0 * W), (int)(W / 4));
    f2h_kernel<<<(int)(W / 4 + 255) / 256, blk>>>((const float4*)Wk, (uint2*)(wh + 1 * W), (int)(W / 4));
    f2h_kernel<<<(int)(W / 4 + 255) / 256, blk>>>((const float4*)Wv, (uint2*)(wh + 2 * W), (int)(W / 4));
    f2h_kernel<<<(int)(W / 4 + 255) / 256, blk>>>((const float4*)Wo, (uint2*)(wh + 3 * W), (int)(W / 4));

    // Q/K/V projections (all fp16, pipelined)
    cudaFuncSetAttribute(gemm_h<true>,  cudaFuncAttributeMaxDynamicSharedMemorySize, GEMM_SMEM_BYTES);
    cudaFuncSetAttribute(gemm_h<false>, cudaFuncAttributeMaxDynamicSharedMemorySize, GEMM_SMEM_BYTES);
    const dim3 gproj(DD / 128, (BB * SS) / 128, 1);
    gemm_h<true><<<gproj, blk, GEMM_SMEM_BYTES>>>(xh, wh + 0 * W, q);
    gemm_h<true><<<gproj, blk, GEMM_SMEM_BYTES>>>(xh, wh + 1 * W, k);
    gemm_h<true><<<gproj, blk, GEMM_SMEM_BYTES>>>(xh, wh + 2 * W, v);

    // fused attention
    const dim3 gatt(SS / 64, BB * HH);
    if (want_attn) {
        cudaFuncSetAttribute(attn_kernel<true>, cudaFuncAttributeMaxDynamicSharedMemorySize, SM_BYTES);
        attn_kernel<true><<<gatt, 256, SM_BYTES>>>(q, k, v, attn, ctx);
    } else {
        cudaFuncSetAttribute(attn_kernel<false>, cudaFuncAttributeMaxDynamicSharedMemorySize, SM_BYTES);
        attn_kernel<false><<<gatt, 256, SM_BYTES>>>(q, k, v, attn, ctx);
    }

    // output projection (fp16 in, fp32 out)
    gemm_h<false><<<gproj, blk, GEMM_SMEM_BYTES>>>(ctx, wh + 3 * W, po);

    // bias + residual + LayerNorm -> y
    ln_kernel<<<BB * SS, blk>>>(po, x, bo, gamma, beta, yout);
}